// round 1
// baseline (speedup 1.0000x reference)
#include <cuda_runtime.h>
#include <cuda_bf16.h>

#define NS 3
#define NQ 64
#define NX 128
#define NY 128
#define NZ 32
#define NN (NX*NY*NZ)      // 524288
#define NW (NN/32)         // 16384 packed words per row
#define NC 21
#define IOU_T 0.2f
#define WCH 256            // word chunk for inter kernel

// ---------------- scratch (device globals; no allocation) ----------------
__device__ unsigned g_mask [NS*NQ*NW];   // packed (sigmoid > 0.5) masks, all subnets
__device__ unsigned g_mask2[NQ*NW];      // packed merged-anchor mask after iter 1
__device__ unsigned g_occ  [NW];         // packed occupancy bits
__device__ int g_cnt [NS*NQ];
__device__ int g_cnt2[NQ];
__device__ int g_inter1[NQ*NQ];
__device__ int g_inter2[NQ*NQ];
__device__ int g_idx1[NQ], g_m1[NQ], g_idx2[NQ], g_m2[NQ], g_keep[NQ];
__device__ float g_iou1[NQ];

__device__ __forceinline__ float sigf(float x){ return 1.0f/(1.0f + __expf(-x)); }

// ---------------- zero the atomic accumulators ----------------
__global__ void init_kernel(){
    int t = blockIdx.x*256 + threadIdx.x;
    if (t < NQ*NQ){ g_inter1[t] = 0; g_inter2[t] = 0; }
}

// ---------------- pass 1: pack (sigmoid(logit) > 0.5) bits, all subnets ----------------
// grid (NN/1024, NQ, NS), 256 threads; 4 elements/thread for MLP
__global__ void mask_kernel(const float* __restrict__ vl){
    int s = blockIdx.z, q = blockIdx.y;
    size_t rowoff = (size_t)(s*NQ + q) * NN;
    int base = blockIdx.x * 1024;
    int t = threadIdx.x;
    float x[4];
    #pragma unroll
    for (int j = 0; j < 4; j++) x[j] = vl[rowoff + base + j*256 + t];
    unsigned w[4];
    #pragma unroll
    for (int j = 0; j < 4; j++) w[j] = __ballot_sync(0xffffffffu, sigf(x[j]) > 0.5f);
    if ((t & 31) == 0){
        size_t mrow = (size_t)(s*NQ + q) * NW;
        int wb = (base >> 5) + (t >> 5);
        #pragma unroll
        for (int j = 0; j < 4; j++) g_mask[mrow + wb + j*8] = w[j];
    }
}

// ---------------- popcount per mask row ----------------
__global__ void cnt_kernel(int round){
    int row = blockIdx.x;
    const unsigned* m = (round == 0) ? (g_mask + (size_t)row * NW)
                                     : (g_mask2 + (size_t)row * NW);
    int s = 0;
    for (int w = threadIdx.x; w < NW; w += 256) s += __popc(m[w]);
    s += __shfl_xor_sync(0xffffffffu, s, 16);
    s += __shfl_xor_sync(0xffffffffu, s, 8);
    s += __shfl_xor_sync(0xffffffffu, s, 4);
    s += __shfl_xor_sync(0xffffffffu, s, 2);
    s += __shfl_xor_sync(0xffffffffu, s, 1);
    __shared__ int sh[8];
    if ((threadIdx.x & 31) == 0) sh[threadIdx.x >> 5] = s;
    __syncthreads();
    if (threadIdx.x == 0){
        int tot = 0;
        #pragma unroll
        for (int i = 0; i < 8; i++) tot += sh[i];
        if (round == 0) g_cnt[row] = tot; else g_cnt2[row] = tot;
    }
}

// ---------------- bit-popcount GEMM: inter[q][p] = popc(A[q] & B[p]) ----------------
// grid (NW/WCH, NQ/16, NQ/16), block 256 = one thread per (qi,pi) pair
__global__ void inter_kernel(int round){
    __shared__ unsigned sA[16][WCH+1];
    __shared__ unsigned sB[16][WCH+1];
    const unsigned* A = (round == 0) ? g_mask : g_mask2;
    const unsigned* B = (round == 0) ? (g_mask + (size_t)NQ*NW)
                                     : (g_mask + (size_t)2*NQ*NW);
    int* inter = (round == 0) ? g_inter1 : g_inter2;
    int w0 = blockIdx.x * WCH;
    int q0 = blockIdx.y * 16, p0 = blockIdx.z * 16;
    int t = threadIdx.x;
    for (int i = t; i < 16*WCH; i += 256){
        int r = i >> 8, w = i & (WCH-1);
        sA[r][w] = A[(size_t)(q0 + r) * NW + w0 + w];
        sB[r][w] = B[(size_t)(p0 + r) * NW + w0 + w];
    }
    __syncthreads();
    int qi = t >> 4, pi = t & 15;
    int s0 = 0, s1 = 0, s2 = 0, s3 = 0;
    #pragma unroll 8
    for (int w = 0; w < WCH; w += 4){
        s0 += __popc(sA[qi][w  ] & sB[pi][w  ]);
        s1 += __popc(sA[qi][w+1] & sB[pi][w+1]);
        s2 += __popc(sA[qi][w+2] & sB[pi][w+2]);
        s3 += __popc(sA[qi][w+3] & sB[pi][w+3]);
    }
    atomicAdd(&inter[(q0 + qi)*NQ + (p0 + pi)], s0 + s1 + s2 + s3);
}

// ---------------- argmax over IoU row, round 1 ----------------
__global__ void match1_kernel(){
    int q = threadIdx.x;   // 64 threads
    float ca = (float)g_cnt[q];            // subnet 0, row q
    float best = -1.0f; int bi = 0;
    for (int p = 0; p < NQ; p++){
        float in = (float)g_inter1[q*NQ + p];
        float un = ca + (float)g_cnt[NQ + p] - in;
        float io = in / fmaxf(un, 1.0f);
        if (io > best){ best = io; bi = p; }   // strict > keeps first index (jnp.argmax)
    }
    g_idx1[q] = bi;
    g_m1[q]   = best > IOU_T;
    g_iou1[q] = best;
}

// ---------------- pass 2: merged-anchor mask bits ----------------
// a1 = matched1 ? (sig(l0)+sig(l1[idx1]))/2 : sig(l0);  bit = a1 > 0.5
__global__ void mask2_kernel(const float* __restrict__ vl){
    int q = blockIdx.y;
    int base = blockIdx.x * 1024;
    int t = threadIdx.x;
    int p = g_idx1[q], m = g_m1[q];
    size_t r0 = (size_t)q * NN;
    size_t r1 = (size_t)(NQ + p) * NN;
    unsigned w[4];
    #pragma unroll
    for (int j = 0; j < 4; j++){
        int e = base + j*256 + t;
        float a = sigf(vl[r0 + e]);
        if (m) a = (a + sigf(vl[r1 + e])) * 0.5f;
        w[j] = __ballot_sync(0xffffffffu, a > 0.5f);
    }
    if ((t & 31) == 0){
        int wb = (base >> 5) + (t >> 5);
        #pragma unroll
        for (int j = 0; j < 4; j++) g_mask2[(size_t)q*NW + wb + j*8] = w[j];
    }
}

// ---------------- argmax round 2 + keep ----------------
__global__ void match2_kernel(){
    int q = threadIdx.x;
    float ca = (float)g_cnt2[q];
    float best = -1.0f; int bi = 0;
    for (int p = 0; p < NQ; p++){
        float in = (float)g_inter2[q*NQ + p];
        float un = ca + (float)g_cnt[2*NQ + p] - in;
        float io = in / fmaxf(un, 1.0f);
        if (io > best){ best = io; bi = p; }
    }
    g_idx2[q] = bi;
    g_m2[q]   = best > IOU_T;
    g_keep[q] = ((g_iou1[q] + best) * 0.5f) > IOU_T;   // mean of the two IoUs
}

// ---------------- occupancy bits: argmax_c sem[c,n] != 0 ----------------
// argmax==0 iff sem[0] >= all others, so occ = exists c>=1 with sem[c] > sem[0]
__global__ void occ_kernel(const float* __restrict__ sem){
    int n = blockIdx.x*256 + threadIdx.x;
    float v0 = sem[n];
    bool o = false;
    #pragma unroll
    for (int c = 1; c < NC; c++) o |= (sem[(size_t)c*NN + n] > v0);
    unsigned b = __ballot_sync(0xffffffffu, o);
    if ((threadIdx.x & 31) == 0) g_occ[n >> 5] = b;
}

// ---------------- pass 3: final output ----------------
__global__ void out_kernel(const float* __restrict__ vl, float* __restrict__ out){
    int q = blockIdx.y;
    int base = blockIdx.x * 1024;
    int t = threadIdx.x;
    size_t orow = (size_t)q * NN;
    if (!g_keep[q]){
        #pragma unroll
        for (int j = 0; j < 4; j++) out[orow + base + j*256 + t] = 0.0f;
        return;
    }
    int m1 = g_m1[q], m2 = g_m2[q];
    size_t r0 = orow;
    size_t r1 = (size_t)(NQ   + g_idx1[q]) * NN;
    size_t r2 = (size_t)(2*NQ + g_idx2[q]) * NN;
    #pragma unroll
    for (int j = 0; j < 4; j++){
        int e = base + j*256 + t;
        float a = sigf(vl[r0 + e]);
        if (m1) a = (a + sigf(vl[r1 + e])) * 0.5f;
        if (m2) a = (a*2.0f + sigf(vl[r2 + e])) * (1.0f/3.0f);
        unsigned ob = g_occ[e >> 5];
        if (!((ob >> (e & 31)) & 1)) a = 0.0f;
        out[orow + e] = a;
    }
}

// ---------------- launch ----------------
extern "C" void kernel_launch(void* const* d_in, const int* in_sizes, int n_in,
                              void* d_out, int out_size){
    const float* vl  = (const float*)d_in[0];   // voxel_logits [3,64,128,128,32]
    const float* sem = (const float*)d_in[2];   // sem_prob_dense [21,128,128,32]
    float* out = (float*)d_out;                 // [64,128,128,32]

    init_kernel <<< 16, 256 >>> ();
    mask_kernel <<< dim3(NN/1024, NQ, NS), 256 >>> (vl);
    cnt_kernel  <<< NS*NQ, 256 >>> (0);
    inter_kernel<<< dim3(NW/WCH, NQ/16, NQ/16), 256 >>> (0);
    match1_kernel<<< 1, NQ >>> ();
    mask2_kernel<<< dim3(NN/1024, NQ), 256 >>> (vl);
    cnt_kernel  <<< NQ, 256 >>> (1);
    inter_kernel<<< dim3(NW/WCH, NQ/16, NQ/16), 256 >>> (1);
    match2_kernel<<< 1, NQ >>> ();
    occ_kernel  <<< NN/256, 256 >>> (sem);
    out_kernel  <<< dim3(NN/1024, NQ), 256 >>> (vl, out);
}

// round 2
// speedup vs baseline: 1.4842x; 1.4842x over previous
#include <cuda_runtime.h>
#include <cuda_fp16.h>

#define NS 3
#define NQ 64
#define NN (128*128*32)    // 524288
#define NN4 (NN/4)         // float4 per row
#define NW (NN/32)         // 16384 packed words per row
#define NC 21
#define IOU_T 0.2f
#define WCH 256

// ---------------- scratch (device globals; no allocation) ----------------
__device__ unsigned g_mask [NS*NQ*NW];
__device__ unsigned g_mask2[NQ*NW];
__device__ unsigned g_occ  [NW];
__device__ __half2  g_a1   [(size_t)NQ*NN/2];   // merged anchor after iter1 (fp16)
__device__ int g_cnt [NS*NQ];
__device__ int g_cnt2[NQ];
__device__ int g_inter1[NQ*NQ];
__device__ int g_inter2[NQ*NQ];
__device__ int g_idx1[NQ], g_m1[NQ], g_idx2[NQ], g_m2[NQ], g_keep[NQ];
__device__ float g_iou1[NQ];

__device__ __forceinline__ float sigf(float x){ return 1.0f/(1.0f + __expf(-x)); }

// ---------------- zero accumulators ----------------
__global__ void init_kernel(){
    int t = blockIdx.x*256 + threadIdx.x;
    if (t < NQ*NQ){ g_inter1[t] = 0; g_inter2[t] = 0; }
    if (t < NS*NQ) g_cnt[t] = 0;
    if (t < NQ)    g_cnt2[t] = 0;
}

// ---------------- pass 1: pack (logit > 0) bits + fused popcount ----------------
// grid (NN4/1024, NQ, NS), 256 threads, 4 float4 per thread
__global__ void mask_kernel(const float4* __restrict__ vl4){
    int s = blockIdx.z, q = blockIdx.y;
    int row = s*NQ + q;
    size_t row4 = (size_t)row * NN4;
    size_t mrow = (size_t)row * NW;
    int t = threadIdx.x, lane = t & 31;
    int cnt = 0;
    #pragma unroll
    for (int j = 0; j < 4; j++){
        int f = blockIdx.x*1024 + j*256 + t;
        float4 v = vl4[row4 + f];
        unsigned nib = (unsigned)(v.x > 0.f) | ((unsigned)(v.y > 0.f) << 1)
                     | ((unsigned)(v.z > 0.f) << 2) | ((unsigned)(v.w > 0.f) << 3);
        cnt += __popc(nib);
        unsigned part = nib << ((lane & 7) * 4);
        part |= __shfl_xor_sync(~0u, part, 1);
        part |= __shfl_xor_sync(~0u, part, 2);
        part |= __shfl_xor_sync(~0u, part, 4);
        if ((lane & 7) == 0) g_mask[mrow + (f >> 3)] = part;
    }
    cnt += __shfl_xor_sync(~0u, cnt, 16);
    cnt += __shfl_xor_sync(~0u, cnt, 8);
    cnt += __shfl_xor_sync(~0u, cnt, 4);
    cnt += __shfl_xor_sync(~0u, cnt, 2);
    cnt += __shfl_xor_sync(~0u, cnt, 1);
    if (lane == 0) atomicAdd(&g_cnt[row], cnt);
}

// ---------------- bit-popcount GEMM, 2x2 register tiling + uint4 ----------------
// grid (NW/WCH, 4, 4), block 256: 8x8 thread tile x 4 word-slices
__global__ void inter_kernel(int round){
    __shared__ unsigned sA[16][WCH+4];
    __shared__ unsigned sB[16][WCH+4];
    const unsigned* A = round ? g_mask2 : g_mask;
    const unsigned* B = g_mask + (size_t)(round ? 2 : 1) * NQ * NW;
    int* inter = round ? g_inter2 : g_inter1;
    int w0 = blockIdx.x * WCH;
    int q0 = blockIdx.y * 16, p0 = blockIdx.z * 16;
    int t = threadIdx.x;
    for (int i = t; i < 16*64; i += 256){
        int r = i >> 6, c = i & 63;
        *(uint4*)&sA[r][c*4] = *(const uint4*)&A[(size_t)(q0 + r) * NW + w0 + c*4];
        *(uint4*)&sB[r][c*4] = *(const uint4*)&B[(size_t)(p0 + r) * NW + w0 + c*4];
    }
    __syncthreads();
    int px = t & 7, qx = (t >> 3) & 7, ws = t >> 6;
    int q = 2*qx, p = 2*px;
    int wbeg = ws * 64;
    int s00 = 0, s01 = 0, s10 = 0, s11 = 0;
    #pragma unroll 4
    for (int w = wbeg; w < wbeg + 64; w += 4){
        uint4 a0 = *(uint4*)&sA[q  ][w];
        uint4 a1 = *(uint4*)&sA[q+1][w];
        uint4 b0 = *(uint4*)&sB[p  ][w];
        uint4 b1 = *(uint4*)&sB[p+1][w];
        s00 += __popc(a0.x&b0.x) + __popc(a0.y&b0.y) + __popc(a0.z&b0.z) + __popc(a0.w&b0.w);
        s01 += __popc(a0.x&b1.x) + __popc(a0.y&b1.y) + __popc(a0.z&b1.z) + __popc(a0.w&b1.w);
        s10 += __popc(a1.x&b0.x) + __popc(a1.y&b0.y) + __popc(a1.z&b0.z) + __popc(a1.w&b0.w);
        s11 += __popc(a1.x&b1.x) + __popc(a1.y&b1.y) + __popc(a1.z&b1.z) + __popc(a1.w&b1.w);
    }
    atomicAdd(&inter[(q0+q  )*NQ + p0+p  ], s00);
    atomicAdd(&inter[(q0+q  )*NQ + p0+p+1], s01);
    atomicAdd(&inter[(q0+q+1)*NQ + p0+p  ], s10);
    atomicAdd(&inter[(q0+q+1)*NQ + p0+p+1], s11);
}

// ---------------- round 1 argmax ----------------
__global__ void match1_kernel(){
    int q = threadIdx.x;
    float ca = (float)g_cnt[q];
    float best = -1.0f; int bi = 0;
    for (int p = 0; p < NQ; p++){
        float in = (float)g_inter1[q*NQ + p];
        float un = ca + (float)g_cnt[NQ + p] - in;
        float io = in / fmaxf(un, 1.0f);
        if (io > best){ best = io; bi = p; }
    }
    g_idx1[q] = bi;
    g_m1[q]   = best > IOU_T;
    g_iou1[q] = best;
}

// ---------------- pass 2: merged anchor -> fp16 a1 + mask bits + count ----------------
__global__ void mask2_kernel(const float4* __restrict__ vl4){
    int q = blockIdx.y;
    int t = threadIdx.x, lane = t & 31;
    int p = g_idx1[q], m = g_m1[q];
    size_t r0 = (size_t)q * NN4;
    size_t r1 = (size_t)(NQ + p) * NN4;
    __half2* a1p = g_a1 + (size_t)q * (NN/2);
    int cnt = 0;
    #pragma unroll
    for (int j = 0; j < 4; j++){
        int f = blockIdx.x*1024 + j*256 + t;
        float4 v0 = vl4[r0 + f];
        float4 a;
        a.x = sigf(v0.x); a.y = sigf(v0.y); a.z = sigf(v0.z); a.w = sigf(v0.w);
        if (m){
            float4 v1 = vl4[r1 + f];
            a.x = (a.x + sigf(v1.x)) * 0.5f;
            a.y = (a.y + sigf(v1.y)) * 0.5f;
            a.z = (a.z + sigf(v1.z)) * 0.5f;
            a.w = (a.w + sigf(v1.w)) * 0.5f;
        }
        __half2 h01 = __floats2half2_rn(a.x, a.y);
        __half2 h23 = __floats2half2_rn(a.z, a.w);
        uint2 hv; hv.x = *(unsigned*)&h01; hv.y = *(unsigned*)&h23;
        *(uint2*)&a1p[(size_t)f*2] = hv;
        unsigned nib = (unsigned)(a.x > 0.5f) | ((unsigned)(a.y > 0.5f) << 1)
                     | ((unsigned)(a.z > 0.5f) << 2) | ((unsigned)(a.w > 0.5f) << 3);
        cnt += __popc(nib);
        unsigned part = nib << ((lane & 7) * 4);
        part |= __shfl_xor_sync(~0u, part, 1);
        part |= __shfl_xor_sync(~0u, part, 2);
        part |= __shfl_xor_sync(~0u, part, 4);
        if ((lane & 7) == 0) g_mask2[(size_t)q*NW + (f >> 3)] = part;
    }
    cnt += __shfl_xor_sync(~0u, cnt, 16);
    cnt += __shfl_xor_sync(~0u, cnt, 8);
    cnt += __shfl_xor_sync(~0u, cnt, 4);
    cnt += __shfl_xor_sync(~0u, cnt, 2);
    cnt += __shfl_xor_sync(~0u, cnt, 1);
    if (lane == 0) atomicAdd(&g_cnt2[q], cnt);
}

// ---------------- round 2 argmax + keep ----------------
__global__ void match2_kernel(){
    int q = threadIdx.x;
    float ca = (float)g_cnt2[q];
    float best = -1.0f; int bi = 0;
    for (int p = 0; p < NQ; p++){
        float in = (float)g_inter2[q*NQ + p];
        float un = ca + (float)g_cnt[2*NQ + p] - in;
        float io = in / fmaxf(un, 1.0f);
        if (io > best){ best = io; bi = p; }
    }
    g_idx2[q] = bi;
    g_m2[q]   = best > IOU_T;
    g_keep[q] = ((g_iou1[q] + best) * 0.5f) > IOU_T;
}

// ---------------- occupancy bits (vectorized) ----------------
__global__ void occ_kernel(const float4* __restrict__ sem4){
    int f = blockIdx.x*256 + threadIdx.x;   // float4 index, NN4 total
    int lane = threadIdx.x & 31;
    float4 v0 = sem4[f];
    unsigned nib = 0;
    #pragma unroll
    for (int c = 1; c < NC; c++){
        float4 vc = sem4[(size_t)c*NN4 + f];
        nib |= (unsigned)(vc.x > v0.x) | ((unsigned)(vc.y > v0.y) << 1)
             | ((unsigned)(vc.z > v0.z) << 2) | ((unsigned)(vc.w > v0.w) << 3);
    }
    unsigned part = nib << ((lane & 7) * 4);
    part |= __shfl_xor_sync(~0u, part, 1);
    part |= __shfl_xor_sync(~0u, part, 2);
    part |= __shfl_xor_sync(~0u, part, 4);
    if ((lane & 7) == 0) g_occ[f >> 3] = part;
}

// ---------------- pass 3: final output (vectorized) ----------------
__global__ void out_kernel(const float4* __restrict__ vl4, float4* __restrict__ out4){
    int q = blockIdx.y;
    int t = threadIdx.x;
    size_t orow4 = (size_t)q * NN4;
    int keep = g_keep[q];
    int m2 = g_m2[q];
    size_t r2 = (size_t)(2*NQ + g_idx2[q]) * NN4;
    const __half2* a1p = g_a1 + (size_t)q * (NN/2);
    #pragma unroll
    for (int j = 0; j < 4; j++){
        int f = blockIdx.x*1024 + j*256 + t;
        float4 o = make_float4(0.f, 0.f, 0.f, 0.f);
        if (keep){
            uint2 hv = *(const uint2*)&a1p[(size_t)f*2];
            float2 a01 = __half22float2(*(__half2*)&hv.x);
            float2 a23 = __half22float2(*(__half2*)&hv.y);
            float4 a = make_float4(a01.x, a01.y, a23.x, a23.y);
            if (m2){
                float4 v2 = vl4[r2 + f];
                a.x = (a.x*2.f + sigf(v2.x)) * (1.f/3.f);
                a.y = (a.y*2.f + sigf(v2.y)) * (1.f/3.f);
                a.z = (a.z*2.f + sigf(v2.z)) * (1.f/3.f);
                a.w = (a.w*2.f + sigf(v2.w)) * (1.f/3.f);
            }
            unsigned ob = g_occ[f >> 3] >> ((f & 7) * 4);
            o.x = (ob & 1u) ? a.x : 0.f;
            o.y = (ob & 2u) ? a.y : 0.f;
            o.z = (ob & 4u) ? a.z : 0.f;
            o.w = (ob & 8u) ? a.w : 0.f;
        }
        out4[orow4 + f] = o;
    }
}

// ---------------- launch ----------------
extern "C" void kernel_launch(void* const* d_in, const int* in_sizes, int n_in,
                              void* d_out, int out_size){
    const float4* vl4  = (const float4*)d_in[0];   // voxel_logits [3,64,128,128,32]
    const float4* sem4 = (const float4*)d_in[2];   // sem_prob_dense [21,128,128,32]
    float4* out4 = (float4*)d_out;                 // [64,128,128,32]

    init_kernel <<< 16, 256 >>> ();
    mask_kernel <<< dim3(NN4/1024, NQ, NS), 256 >>> (vl4);
    inter_kernel<<< dim3(NW/WCH, NQ/16, NQ/16), 256 >>> (0);
    match1_kernel<<< 1, NQ >>> ();
    mask2_kernel<<< dim3(NN4/1024, NQ), 256 >>> (vl4);
    inter_kernel<<< dim3(NW/WCH, NQ/16, NQ/16), 256 >>> (1);
    match2_kernel<<< 1, NQ >>> ();
    occ_kernel  <<< NN4/256, 256 >>> (sem4);
    out_kernel  <<< dim3(NN4/1024, NQ), 256 >>> (vl4, out4);
}

// round 4
// speedup vs baseline: 1.5199x; 1.0240x over previous
#include <cuda_runtime.h>
#include <cuda_fp16.h>

#define NS 3
#define NQ 64
#define NN (128*128*32)    // 524288
#define NN4 (NN/4)         // 131072 float4 per row
#define NW (NN/32)         // 16384 packed words per row
#define NC 21
#define IOU_T 0.2f
#define WCH 256

// ---------------- scratch (device globals; no allocation) ----------------
__device__ unsigned g_mask [NS*NQ*NW];
__device__ unsigned g_mask2[NQ*NW];
__device__ unsigned g_occ  [NW];
__device__ uint2    g_a1   [(size_t)NQ*NN4];   // merged anchor after iter1, fp16x4 (output path only)
__device__ int g_cnt [NS*NQ];
__device__ int g_cnt2[NQ];
__device__ int g_inter1[NQ*NQ];
__device__ int g_inter2[NQ*NQ];
__device__ int g_idx1[NQ], g_m1[NQ], g_idx2[NQ], g_m2[NQ], g_keep[NQ];
__device__ float g_iou1[NQ];

__device__ __forceinline__ float sigf(float x){ return 1.0f/(1.0f + __expf(-x)); }

__device__ __forceinline__ uint2 pack4h(float a, float b, float c, float d){
    __half2 h01 = __floats2half2_rn(a, b);
    __half2 h23 = __floats2half2_rn(c, d);
    uint2 r; r.x = *(unsigned*)&h01; r.y = *(unsigned*)&h23; return r;
}
__device__ __forceinline__ float4 unpack4h(uint2 hv){
    float2 a01 = __half22float2(*(__half2*)&hv.x);
    float2 a23 = __half22float2(*(__half2*)&hv.y);
    return make_float4(a01.x, a01.y, a23.x, a23.y);
}

// ---------------- zero accumulators ----------------
__global__ void init_kernel(){
    int t = blockIdx.x*256 + threadIdx.x;
    if (t < NQ*NQ){ g_inter1[t] = 0; g_inter2[t] = 0; }
    if (t < NS*NQ) g_cnt[t] = 0;
    if (t < NQ)    g_cnt2[t] = 0;
}

// ---------------- occupancy bits (runs first; pure streaming) ----------------
__global__ void occ_kernel(const float4* __restrict__ sem4){
    int f = blockIdx.x*256 + threadIdx.x;
    int lane = threadIdx.x & 31;
    float4 v0 = __ldcs(&sem4[f]);
    unsigned nib = 0;
    #pragma unroll
    for (int c = 1; c < NC; c++){
        float4 vc = __ldcs(&sem4[(size_t)c*NN4 + f]);
        nib |= (unsigned)(vc.x > v0.x) | ((unsigned)(vc.y > v0.y) << 1)
             | ((unsigned)(vc.z > v0.z) << 2) | ((unsigned)(vc.w > v0.w) << 3);
    }
    unsigned part = nib << ((lane & 7) * 4);
    part |= __shfl_xor_sync(~0u, part, 1);
    part |= __shfl_xor_sync(~0u, part, 2);
    part |= __shfl_xor_sync(~0u, part, 4);
    if ((lane & 7) == 0) g_occ[f >> 3] = part;
}

// ---------------- pass 1: pack (logit>0) bits + fused count ----------------
__global__ void mask_kernel(const float4* __restrict__ vl4){
    int s = blockIdx.z, q = blockIdx.y;
    int row = s*NQ + q;
    size_t row4 = (size_t)row * NN4;
    size_t mrow = (size_t)row * NW;
    int t = threadIdx.x, lane = t & 31;
    int cnt = 0;
    #pragma unroll
    for (int j = 0; j < 4; j++){
        int f = blockIdx.x*1024 + j*256 + t;
        float4 v = __ldcs(&vl4[row4 + f]);
        unsigned nib = (unsigned)(v.x > 0.f) | ((unsigned)(v.y > 0.f) << 1)
                     | ((unsigned)(v.z > 0.f) << 2) | ((unsigned)(v.w > 0.f) << 3);
        cnt += __popc(nib);
        unsigned part = nib << ((lane & 7) * 4);
        part |= __shfl_xor_sync(~0u, part, 1);
        part |= __shfl_xor_sync(~0u, part, 2);
        part |= __shfl_xor_sync(~0u, part, 4);
        if ((lane & 7) == 0) g_mask[mrow + (f >> 3)] = part;
    }
    cnt += __shfl_xor_sync(~0u, cnt, 16);
    cnt += __shfl_xor_sync(~0u, cnt, 8);
    cnt += __shfl_xor_sync(~0u, cnt, 4);
    cnt += __shfl_xor_sync(~0u, cnt, 2);
    cnt += __shfl_xor_sync(~0u, cnt, 1);
    if (lane == 0) atomicAdd(&g_cnt[row], cnt);
}

// ---------------- bit-popcount GEMM: inter[q][p] = popc(A[q] & B[p]) ----------------
__global__ void inter_kernel(int round){
    __shared__ unsigned sA[16][WCH+4];
    __shared__ unsigned sB[16][WCH+4];
    const unsigned* A = round ? g_mask2 : g_mask;
    const unsigned* B = g_mask + (size_t)(round ? 2 : 1) * NQ * NW;
    int* inter = round ? g_inter2 : g_inter1;
    int w0 = blockIdx.x * WCH;
    int q0 = blockIdx.y * 16, p0 = blockIdx.z * 16;
    int t = threadIdx.x;
    for (int i = t; i < 16*64; i += 256){
        int r = i >> 6, c = i & 63;
        *(uint4*)&sA[r][c*4] = *(const uint4*)&A[(size_t)(q0 + r) * NW + w0 + c*4];
        *(uint4*)&sB[r][c*4] = *(const uint4*)&B[(size_t)(p0 + r) * NW + w0 + c*4];
    }
    __syncthreads();
    int px = t & 7, qx = (t >> 3) & 7, ws = t >> 6;
    int q = 2*qx, p = 2*px;
    int wbeg = ws * 64;
    int s00 = 0, s01 = 0, s10 = 0, s11 = 0;
    #pragma unroll 4
    for (int w = wbeg; w < wbeg + 64; w += 4){
        uint4 a0 = *(uint4*)&sA[q  ][w];
        uint4 a1 = *(uint4*)&sA[q+1][w];
        uint4 b0 = *(uint4*)&sB[p  ][w];
        uint4 b1 = *(uint4*)&sB[p+1][w];
        s00 += __popc(a0.x&b0.x) + __popc(a0.y&b0.y) + __popc(a0.z&b0.z) + __popc(a0.w&b0.w);
        s01 += __popc(a0.x&b1.x) + __popc(a0.y&b1.y) + __popc(a0.z&b1.z) + __popc(a0.w&b1.w);
        s10 += __popc(a1.x&b0.x) + __popc(a1.y&b0.y) + __popc(a1.z&b0.z) + __popc(a1.w&b0.w);
        s11 += __popc(a1.x&b1.x) + __popc(a1.y&b1.y) + __popc(a1.z&b1.z) + __popc(a1.w&b1.w);
    }
    atomicAdd(&inter[(q0+q  )*NQ + p0+p  ], s00);
    atomicAdd(&inter[(q0+q  )*NQ + p0+p+1], s01);
    atomicAdd(&inter[(q0+q+1)*NQ + p0+p  ], s10);
    atomicAdd(&inter[(q0+q+1)*NQ + p0+p+1], s11);
}

// ---------------- parallel argmax: one warp per q (first-index tie-break) ----------------
__global__ void match_kernel(int round){
    int q = blockIdx.x*8 + (threadIdx.x >> 5);
    int lane = threadIdx.x & 31;
    const int* inter = round ? g_inter2 : g_inter1;
    const int* cb    = g_cnt + (round ? 2*NQ : NQ);
    float ca = (float)(round ? g_cnt2[q] : g_cnt[q]);
    float best = -1.0f; int bi = 0;
    #pragma unroll
    for (int k = 0; k < 2; k++){
        int p = lane + k*32;
        float in = (float)inter[q*NQ + p];
        float un = ca + (float)cb[p] - in;
        float io = in / fmaxf(un, 1.0f);
        if (io > best){ best = io; bi = p; }
    }
    #pragma unroll
    for (int d = 16; d; d >>= 1){
        float ob = __shfl_xor_sync(~0u, best, d);
        int   oi = __shfl_xor_sync(~0u, bi,   d);
        if (ob > best || (ob == best && oi < bi)){ best = ob; bi = oi; }
    }
    if (lane == 0){
        if (round == 0){
            g_idx1[q] = bi; g_m1[q] = best > IOU_T; g_iou1[q] = best;
        } else {
            g_idx2[q] = bi; g_m2[q] = best > IOU_T;
            g_keep[q] = ((g_iou1[q] + best) * 0.5f) > IOU_T;
        }
    }
}

// ---------------- pass 2: merged anchor (fp32-exact bits) + fp16 a1 + count ----------------
__global__ void mask2_kernel(const float4* __restrict__ vl4){
    int q = blockIdx.y;
    int t = threadIdx.x, lane = t & 31;
    int p = g_idx1[q], m = g_m1[q];
    size_t r0 = (size_t)q * NN4;
    size_t r1 = (size_t)(NQ + p) * NN4;
    int cnt = 0;
    #pragma unroll
    for (int j = 0; j < 4; j++){
        int f = blockIdx.x*1024 + j*256 + t;
        float4 v0 = __ldcs(&vl4[r0 + f]);
        float4 a;
        a.x = sigf(v0.x); a.y = sigf(v0.y); a.z = sigf(v0.z); a.w = sigf(v0.w);
        if (m){
            float4 v1 = __ldcs(&vl4[r1 + f]);
            a.x = (a.x + sigf(v1.x)) * 0.5f;
            a.y = (a.y + sigf(v1.y)) * 0.5f;
            a.z = (a.z + sigf(v1.z)) * 0.5f;
            a.w = (a.w + sigf(v1.w)) * 0.5f;
        }
        g_a1[(size_t)q*NN4 + f] = pack4h(a.x, a.y, a.z, a.w);   // fp16 only for OUTPUT path
        unsigned nib = (unsigned)(a.x > 0.5f) | ((unsigned)(a.y > 0.5f) << 1)
                     | ((unsigned)(a.z > 0.5f) << 2) | ((unsigned)(a.w > 0.5f) << 3);
        cnt += __popc(nib);
        unsigned part = nib << ((lane & 7) * 4);
        part |= __shfl_xor_sync(~0u, part, 1);
        part |= __shfl_xor_sync(~0u, part, 2);
        part |= __shfl_xor_sync(~0u, part, 4);
        if ((lane & 7) == 0) g_mask2[(size_t)q*NW + (f >> 3)] = part;
    }
    cnt += __shfl_xor_sync(~0u, cnt, 16);
    cnt += __shfl_xor_sync(~0u, cnt, 8);
    cnt += __shfl_xor_sync(~0u, cnt, 4);
    cnt += __shfl_xor_sync(~0u, cnt, 2);
    cnt += __shfl_xor_sync(~0u, cnt, 1);
    if (lane == 0) atomicAdd(&g_cnt2[q], cnt);
}

// ---------------- pass 3: final output ----------------
__global__ void out_kernel(const float4* __restrict__ vl4, float4* __restrict__ out4){
    int q = blockIdx.y;
    int t = threadIdx.x;
    size_t orow4 = (size_t)q * NN4;
    int keep = g_keep[q];
    int m2 = g_m2[q];
    size_t r2 = (size_t)(2*NQ + g_idx2[q]) * NN4;
    #pragma unroll
    for (int j = 0; j < 4; j++){
        int f = blockIdx.x*1024 + j*256 + t;
        float4 o = make_float4(0.f, 0.f, 0.f, 0.f);
        if (keep){
            float4 a = unpack4h(g_a1[(size_t)q*NN4 + f]);   // mostly L2-hit
            if (m2){
                float4 v2 = __ldcs(&vl4[r2 + f]);
                a.x = (a.x*2.f + sigf(v2.x)) * (1.f/3.f);
                a.y = (a.y*2.f + sigf(v2.y)) * (1.f/3.f);
                a.z = (a.z*2.f + sigf(v2.z)) * (1.f/3.f);
                a.w = (a.w*2.f + sigf(v2.w)) * (1.f/3.f);
            }
            unsigned ob = g_occ[f >> 3] >> ((f & 7) * 4);
            o.x = (ob & 1u) ? a.x : 0.f;
            o.y = (ob & 2u) ? a.y : 0.f;
            o.z = (ob & 4u) ? a.z : 0.f;
            o.w = (ob & 8u) ? a.w : 0.f;
        }
        __stcs(&out4[orow4 + f], o);
    }
}

// ---------------- launch ----------------
extern "C" void kernel_launch(void* const* d_in, const int* in_sizes, int n_in,
                              void* d_out, int out_size){
    const float4* vl4  = (const float4*)d_in[0];   // voxel_logits [3,64,128,128,32]
    const float4* sem4 = (const float4*)d_in[2];   // sem_prob_dense [21,128,128,32]
    float4* out4 = (float4*)d_out;                 // [64,128,128,32]

    init_kernel <<< 16, 256 >>> ();
    occ_kernel  <<< NN4/256, 256 >>> (sem4);
    mask_kernel <<< dim3(NN4/1024, NQ, NS), 256 >>> (vl4);
    inter_kernel<<< dim3(NW/WCH, NQ/16, NQ/16), 256 >>> (0);
    match_kernel<<< 8, 256 >>> (0);
    mask2_kernel<<< dim3(NN4/1024, NQ), 256 >>> (vl4);
    inter_kernel<<< dim3(NW/WCH, NQ/16, NQ/16), 256 >>> (1);
    match_kernel<<< 8, 256 >>> (1);
    out_kernel  <<< dim3(NN4/1024, NQ), 256 >>> (vl4, out4);
}

// round 5
// speedup vs baseline: 1.8867x; 1.2413x over previous
#include <cuda_runtime.h>
#include <cuda_fp16.h>

#define NS 3
#define NQ 64
#define NN (128*128*32)    // 524288
#define NN4 (NN/4)         // 131072 float4 per row
#define NW (NN/32)         // 16384 packed words per row
#define NC 21
#define IOU_T 0.2f
#define WCH 256
#define SROW (WCH+4)       // 260-word smem row stride (bank spread)

// ---------------- scratch (device globals; no allocation) ----------------
__device__ unsigned g_mask [NS*NQ*NW];
__device__ unsigned g_mask2[NQ*NW];
__device__ unsigned g_occ  [NW];
__device__ uint2    g_a1   [(size_t)NQ*NN4];   // merged anchor after iter1, fp16x4 (output path only)
__device__ int g_cnt [NS*NQ];
__device__ int g_cnt2[NQ];
__device__ int g_inter1[NQ*NQ];
__device__ int g_inter2[NQ*NQ];
__device__ int g_idx1[NQ], g_m1[NQ], g_idx2[NQ], g_m2[NQ], g_keep[NQ];
__device__ float g_iou1[NQ];

__device__ __forceinline__ float sigf(float x){ return 1.0f/(1.0f + __expf(-x)); }

__device__ __forceinline__ uint2 pack4h(float a, float b, float c, float d){
    __half2 h01 = __floats2half2_rn(a, b);
    __half2 h23 = __floats2half2_rn(c, d);
    uint2 r; r.x = *(unsigned*)&h01; r.y = *(unsigned*)&h23; return r;
}
__device__ __forceinline__ float4 unpack4h(uint2 hv){
    float2 a01 = __half22float2(*(__half2*)&hv.x);
    float2 a23 = __half22float2(*(__half2*)&hv.y);
    return make_float4(a01.x, a01.y, a23.x, a23.y);
}

// ---------------- zero accumulators ----------------
__global__ void init_kernel(){
    int t = blockIdx.x*256 + threadIdx.x;
    if (t < NQ*NQ){ g_inter1[t] = 0; g_inter2[t] = 0; }
    if (t < NS*NQ) g_cnt[t] = 0;
    if (t < NQ)    g_cnt2[t] = 0;
}

// ---------------- occupancy bits (pure streaming) ----------------
__global__ void occ_kernel(const float4* __restrict__ sem4){
    int f = blockIdx.x*256 + threadIdx.x;
    int lane = threadIdx.x & 31;
    float4 v0 = __ldcs(&sem4[f]);
    unsigned nib = 0;
    #pragma unroll
    for (int c = 1; c < NC; c++){
        float4 vc = __ldcs(&sem4[(size_t)c*NN4 + f]);
        nib |= (unsigned)(vc.x > v0.x) | ((unsigned)(vc.y > v0.y) << 1)
             | ((unsigned)(vc.z > v0.z) << 2) | ((unsigned)(vc.w > v0.w) << 3);
    }
    unsigned part = nib << ((lane & 7) * 4);
    part |= __shfl_xor_sync(~0u, part, 1);
    part |= __shfl_xor_sync(~0u, part, 2);
    part |= __shfl_xor_sync(~0u, part, 4);
    if ((lane & 7) == 0) g_occ[f >> 3] = part;
}

// ---------------- pass 1: pack (logit>0) bits — pure stream, no atomics ----------------
__global__ void mask_kernel(const float4* __restrict__ vl4){
    int s = blockIdx.z, q = blockIdx.y;
    int row = s*NQ + q;
    size_t row4 = (size_t)row * NN4;
    size_t mrow = (size_t)row * NW;
    int t = threadIdx.x, lane = t & 31;
    #pragma unroll
    for (int j = 0; j < 4; j++){
        int f = blockIdx.x*1024 + j*256 + t;
        float4 v = __ldcs(&vl4[row4 + f]);
        unsigned nib = (unsigned)(v.x > 0.f) | ((unsigned)(v.y > 0.f) << 1)
                     | ((unsigned)(v.z > 0.f) << 2) | ((unsigned)(v.w > 0.f) << 3);
        unsigned part = nib << ((lane & 7) * 4);
        part |= __shfl_xor_sync(~0u, part, 1);
        part |= __shfl_xor_sync(~0u, part, 2);
        part |= __shfl_xor_sync(~0u, part, 4);
        if ((lane & 7) == 0) g_mask[mrow + (f >> 3)] = part;
    }
}

// ---------------- bit-popcount GEMM + fused row counts ----------------
// grid (NW/WCH, 4, 4), block 256: 4x4 thread tile (rows strided by 4) x 16 word-slices
__global__ void inter_kernel(int round){
    __shared__ unsigned sA[16*SROW];
    __shared__ unsigned sB[16*SROW];
    const unsigned* A = round ? g_mask2 : g_mask;
    const unsigned* B = g_mask + (size_t)(round ? 2 : 1) * NQ * NW;
    int* inter = round ? g_inter2 : g_inter1;
    int* cntA  = round ? g_cnt2 : g_cnt;
    int* cntB  = g_cnt + (round ? 2 : 1) * NQ;
    int w0 = blockIdx.x * WCH;
    int q0 = blockIdx.y * 16, p0 = blockIdx.z * 16;
    int t = threadIdx.x;
    for (int i = t; i < 16*64; i += 256){
        int r = i >> 6, c = (i & 63) * 4;
        *(uint4*)&sA[r*SROW + c] = *(const uint4*)&A[(size_t)(q0 + r)*NW + w0 + c];
        *(uint4*)&sB[r*SROW + c] = *(const uint4*)&B[(size_t)(p0 + r)*NW + w0 + c];
    }
    __syncthreads();
    // fused per-row popcounts (edge blocks only; replaces mask-kernel atomics)
    if (blockIdx.z == 0){
        int r = t >> 4, part = t & 15;
        int c = 0;
        #pragma unroll
        for (int w = 0; w < 16; w++) c += __popc(sA[r*SROW + part*16 + w]);
        #pragma unroll
        for (int d = 8; d; d >>= 1) c += __shfl_down_sync(~0u, c, d, 16);
        if (part == 0) atomicAdd(&cntA[q0 + r], c);
    }
    if (blockIdx.y == 0){
        int r = t >> 4, part = t & 15;
        int c = 0;
        #pragma unroll
        for (int w = 0; w < 16; w++) c += __popc(sB[r*SROW + part*16 + w]);
        #pragma unroll
        for (int d = 8; d; d >>= 1) c += __shfl_down_sync(~0u, c, d, 16);
        if (part == 0) atomicAdd(&cntB[p0 + r], c);
    }
    // 4x4 register tile; rows strided by 4 -> conflict-free uint4 LDS
    int px = t & 3, qx = (t >> 2) & 3, ws = t >> 4;
    int acc[16];
    #pragma unroll
    for (int k = 0; k < 16; k++) acc[k] = 0;
    int wbeg = ws * 16;
    #pragma unroll
    for (int w = wbeg; w < wbeg + 16; w += 4){
        uint4 a[4], b[4];
        #pragma unroll
        for (int i = 0; i < 4; i++){
            a[i] = *(uint4*)&sA[(qx + 4*i)*SROW + w];
            b[i] = *(uint4*)&sB[(px + 4*i)*SROW + w];
        }
        #pragma unroll
        for (int i = 0; i < 4; i++)
            #pragma unroll
            for (int j = 0; j < 4; j++)
                acc[i*4+j] += __popc(a[i].x & b[j].x) + __popc(a[i].y & b[j].y)
                            + __popc(a[i].z & b[j].z) + __popc(a[i].w & b[j].w);
    }
    __syncthreads();
    int* sRed = (int*)sA;   // reuse: 16 slices x 256 outputs = 16 KB
    #pragma unroll
    for (int i = 0; i < 4; i++)
        #pragma unroll
        for (int j = 0; j < 4; j++)
            sRed[ws*256 + (qx + 4*i)*16 + (px + 4*j)] = acc[i*4+j];
    __syncthreads();
    int s = 0;
    #pragma unroll
    for (int k = 0; k < 16; k++) s += sRed[k*256 + t];
    atomicAdd(&inter[(q0 + (t >> 4))*NQ + p0 + (t & 15)], s);
}

// ---------------- parallel argmax: one warp per q (first-index tie-break) ----------------
__global__ void match_kernel(int round){
    int q = blockIdx.x*8 + (threadIdx.x >> 5);
    int lane = threadIdx.x & 31;
    const int* inter = round ? g_inter2 : g_inter1;
    const int* cb    = g_cnt + (round ? 2*NQ : NQ);
    float ca = (float)(round ? g_cnt2[q] : g_cnt[q]);
    float best = -1.0f; int bi = 0;
    #pragma unroll
    for (int k = 0; k < 2; k++){
        int p = lane + k*32;
        float in = (float)inter[q*NQ + p];
        float un = ca + (float)cb[p] - in;
        float io = in / fmaxf(un, 1.0f);
        if (io > best){ best = io; bi = p; }
    }
    #pragma unroll
    for (int d = 16; d; d >>= 1){
        float ob = __shfl_xor_sync(~0u, best, d);
        int   oi = __shfl_xor_sync(~0u, bi,   d);
        if (ob > best || (ob == best && oi < bi)){ best = ob; bi = oi; }
    }
    if (lane == 0){
        if (round == 0){
            g_idx1[q] = bi; g_m1[q] = best > IOU_T; g_iou1[q] = best;
        } else {
            g_idx2[q] = bi; g_m2[q] = best > IOU_T;
            g_keep[q] = ((g_iou1[q] + best) * 0.5f) > IOU_T;
        }
    }
}

// ---------------- pass 2: merged anchor (fp32-exact bits) + fp16 a1, no atomics ----------------
__global__ void mask2_kernel(const float4* __restrict__ vl4){
    int q = blockIdx.y;
    int t = threadIdx.x, lane = t & 31;
    int p = g_idx1[q], m = g_m1[q];
    size_t r0 = (size_t)q * NN4;
    size_t r1 = (size_t)(NQ + p) * NN4;
    #pragma unroll
    for (int j = 0; j < 4; j++){
        int f = blockIdx.x*1024 + j*256 + t;
        float4 v0 = __ldcs(&vl4[r0 + f]);
        float4 a;
        a.x = sigf(v0.x); a.y = sigf(v0.y); a.z = sigf(v0.z); a.w = sigf(v0.w);
        if (m){
            float4 v1 = __ldcs(&vl4[r1 + f]);
            a.x = (a.x + sigf(v1.x)) * 0.5f;
            a.y = (a.y + sigf(v1.y)) * 0.5f;
            a.z = (a.z + sigf(v1.z)) * 0.5f;
            a.w = (a.w + sigf(v1.w)) * 0.5f;
        }
        g_a1[(size_t)q*NN4 + f] = pack4h(a.x, a.y, a.z, a.w);
        unsigned nib = (unsigned)(a.x > 0.5f) | ((unsigned)(a.y > 0.5f) << 1)
                     | ((unsigned)(a.z > 0.5f) << 2) | ((unsigned)(a.w > 0.5f) << 3);
        unsigned part = nib << ((lane & 7) * 4);
        part |= __shfl_xor_sync(~0u, part, 1);
        part |= __shfl_xor_sync(~0u, part, 2);
        part |= __shfl_xor_sync(~0u, part, 4);
        if ((lane & 7) == 0) g_mask2[(size_t)q*NW + (f >> 3)] = part;
    }
}

// ---------------- pass 3: final output ----------------
__global__ void out_kernel(const float4* __restrict__ vl4, float4* __restrict__ out4){
    int q = blockIdx.y;
    int t = threadIdx.x;
    size_t orow4 = (size_t)q * NN4;
    int keep = g_keep[q];
    int m2 = g_m2[q];
    size_t r2 = (size_t)(2*NQ + g_idx2[q]) * NN4;
    #pragma unroll
    for (int j = 0; j < 4; j++){
        int f = blockIdx.x*1024 + j*256 + t;
        float4 o = make_float4(0.f, 0.f, 0.f, 0.f);
        if (keep){
            float4 a = unpack4h(g_a1[(size_t)q*NN4 + f]);   // mostly L2-hit
            if (m2){
                float4 v2 = __ldcs(&vl4[r2 + f]);
                a.x = (a.x*2.f + sigf(v2.x)) * (1.f/3.f);
                a.y = (a.y*2.f + sigf(v2.y)) * (1.f/3.f);
                a.z = (a.z*2.f + sigf(v2.z)) * (1.f/3.f);
                a.w = (a.w*2.f + sigf(v2.w)) * (1.f/3.f);
            }
            unsigned ob = g_occ[f >> 3] >> ((f & 7) * 4);
            o.x = (ob & 1u) ? a.x : 0.f;
            o.y = (ob & 2u) ? a.y : 0.f;
            o.z = (ob & 4u) ? a.z : 0.f;
            o.w = (ob & 8u) ? a.w : 0.f;
        }
        __stcs(&out4[orow4 + f], o);
    }
}

// ---------------- launch ----------------
extern "C" void kernel_launch(void* const* d_in, const int* in_sizes, int n_in,
                              void* d_out, int out_size){
    const float4* vl4  = (const float4*)d_in[0];   // voxel_logits [3,64,128,128,32]
    const float4* sem4 = (const float4*)d_in[2];   // sem_prob_dense [21,128,128,32]
    float4* out4 = (float4*)d_out;                 // [64,128,128,32]

    init_kernel <<< 16, 256 >>> ();
    occ_kernel  <<< NN4/256, 256 >>> (sem4);
    mask_kernel <<< dim3(NN4/1024, NQ, NS), 256 >>> (vl4);
    inter_kernel<<< dim3(NW/WCH, NQ/16, NQ/16), 256 >>> (0);
    match_kernel<<< 8, 256 >>> (0);
    mask2_kernel<<< dim3(NN4/1024, NQ), 256 >>> (vl4);
    inter_kernel<<< dim3(NW/WCH, NQ/16, NQ/16), 256 >>> (1);
    match_kernel<<< 8, 256 >>> (1);
    out_kernel  <<< dim3(NN4/1024, NQ), 256 >>> (vl4, out4);
}

// round 6
// speedup vs baseline: 1.9048x; 1.0096x over previous
#include <cuda_runtime.h>
#include <cuda_fp16.h>

#define NS 3
#define NQ 64
#define NN (128*128*32)    // 524288
#define NN4 (NN/4)         // 131072 float4 per row
#define NW (NN/32)         // 16384 packed words per row
#define NC 21
#define IOU_T 0.2f
#define WCH 256
#define SROW (WCH+4)       // 260-word smem row stride (bank spread)

// ---------------- scratch (device globals; no allocation) ----------------
__device__ unsigned g_mask [NS*NQ*NW];
__device__ unsigned g_mask2[NQ*NW];
__device__ unsigned g_occ  [NW];
__device__ uint2    g_a1   [(size_t)NQ*NN4];   // merged anchor after iter1, fp16x4 (output path only)
__device__ int g_cnt [NS*NQ];
__device__ int g_cnt2[NQ];
__device__ int g_inter1[NQ*NQ];
__device__ int g_inter2[NQ*NQ];
__device__ int g_idx1[NQ], g_m1[NQ], g_idx2[NQ], g_m2[NQ], g_keep[NQ];
__device__ float g_iou1[NQ];

__device__ __forceinline__ float sigf(float x){ return 1.0f/(1.0f + __expf(-x)); }

__device__ __forceinline__ uint2 pack4h(float a, float b, float c, float d){
    __half2 h01 = __floats2half2_rn(a, b);
    __half2 h23 = __floats2half2_rn(c, d);
    uint2 r; r.x = *(unsigned*)&h01; r.y = *(unsigned*)&h23; return r;
}
__device__ __forceinline__ float4 unpack4h(uint2 hv){
    float2 a01 = __half22float2(*(__half2*)&hv.x);
    float2 a23 = __half22float2(*(__half2*)&hv.y);
    return make_float4(a01.x, a01.y, a23.x, a23.y);
}

// ---------------- zero accumulators ----------------
__global__ void init_kernel(){
    int t = blockIdx.x*256 + threadIdx.x;
    if (t < NQ*NQ){ g_inter1[t] = 0; g_inter2[t] = 0; }
    if (t < NS*NQ) g_cnt[t] = 0;
    if (t < NQ)    g_cnt2[t] = 0;
}

// ---------------- occupancy bits (pure streaming; side stream) ----------------
__global__ void occ_kernel(const float4* __restrict__ sem4){
    int f = blockIdx.x*256 + threadIdx.x;
    int lane = threadIdx.x & 31;
    float4 v0 = __ldcs(&sem4[f]);
    unsigned nib = 0;
    #pragma unroll
    for (int c = 1; c < NC; c++){
        float4 vc = __ldcs(&sem4[(size_t)c*NN4 + f]);
        nib |= (unsigned)(vc.x > v0.x) | ((unsigned)(vc.y > v0.y) << 1)
             | ((unsigned)(vc.z > v0.z) << 2) | ((unsigned)(vc.w > v0.w) << 3);
    }
    unsigned part = nib << ((lane & 7) * 4);
    part |= __shfl_xor_sync(~0u, part, 1);
    part |= __shfl_xor_sync(~0u, part, 2);
    part |= __shfl_xor_sync(~0u, part, 4);
    if ((lane & 7) == 0) g_occ[f >> 3] = part;
}

// ---------------- pass 1: pack (logit>0) bits — pure stream ----------------
__global__ void mask_kernel(const float4* __restrict__ vl4, int s_base){
    int s = blockIdx.z + s_base, q = blockIdx.y;
    int row = s*NQ + q;
    size_t row4 = (size_t)row * NN4;
    size_t mrow = (size_t)row * NW;
    int t = threadIdx.x, lane = t & 31;
    #pragma unroll
    for (int j = 0; j < 4; j++){
        int f = blockIdx.x*1024 + j*256 + t;
        float4 v = __ldcs(&vl4[row4 + f]);
        unsigned nib = (unsigned)(v.x > 0.f) | ((unsigned)(v.y > 0.f) << 1)
                     | ((unsigned)(v.z > 0.f) << 2) | ((unsigned)(v.w > 0.f) << 3);
        unsigned part = nib << ((lane & 7) * 4);
        part |= __shfl_xor_sync(~0u, part, 1);
        part |= __shfl_xor_sync(~0u, part, 2);
        part |= __shfl_xor_sync(~0u, part, 4);
        if ((lane & 7) == 0) g_mask[mrow + (f >> 3)] = part;
    }
}

// ---------------- bit-popcount GEMM + fused row counts ----------------
__global__ void __launch_bounds__(256, 4) inter_kernel(int round){
    __shared__ unsigned sA[16*SROW];
    __shared__ unsigned sB[16*SROW];
    const unsigned* A = round ? g_mask2 : g_mask;
    const unsigned* B = g_mask + (size_t)(round ? 2 : 1) * NQ * NW;
    int* inter = round ? g_inter2 : g_inter1;
    int* cntA  = round ? g_cnt2 : g_cnt;
    int* cntB  = g_cnt + (round ? 2 : 1) * NQ;
    int w0 = blockIdx.x * WCH;
    int q0 = blockIdx.y * 16, p0 = blockIdx.z * 16;
    int t = threadIdx.x;
    for (int i = t; i < 16*64; i += 256){
        int r = i >> 6, c = (i & 63) * 4;
        *(uint4*)&sA[r*SROW + c] = *(const uint4*)&A[(size_t)(q0 + r)*NW + w0 + c];
        *(uint4*)&sB[r*SROW + c] = *(const uint4*)&B[(size_t)(p0 + r)*NW + w0 + c];
    }
    __syncthreads();
    if (blockIdx.z == 0){
        int r = t >> 4, part = t & 15;
        int c = 0;
        #pragma unroll
        for (int w = 0; w < 16; w++) c += __popc(sA[r*SROW + part*16 + w]);
        #pragma unroll
        for (int d = 8; d; d >>= 1) c += __shfl_down_sync(~0u, c, d, 16);
        if (part == 0) atomicAdd(&cntA[q0 + r], c);
    }
    if (blockIdx.y == 0){
        int r = t >> 4, part = t & 15;
        int c = 0;
        #pragma unroll
        for (int w = 0; w < 16; w++) c += __popc(sB[r*SROW + part*16 + w]);
        #pragma unroll
        for (int d = 8; d; d >>= 1) c += __shfl_down_sync(~0u, c, d, 16);
        if (part == 0) atomicAdd(&cntB[p0 + r], c);
    }
    int px = t & 3, qx = (t >> 2) & 3, ws = t >> 4;
    int acc[16];
    #pragma unroll
    for (int k = 0; k < 16; k++) acc[k] = 0;
    int wbeg = ws * 16;
    #pragma unroll
    for (int w = wbeg; w < wbeg + 16; w += 4){
        uint4 a[4], b[4];
        #pragma unroll
        for (int i = 0; i < 4; i++){
            a[i] = *(uint4*)&sA[(qx + 4*i)*SROW + w];
            b[i] = *(uint4*)&sB[(px + 4*i)*SROW + w];
        }
        #pragma unroll
        for (int i = 0; i < 4; i++)
            #pragma unroll
            for (int j = 0; j < 4; j++)
                acc[i*4+j] += __popc(a[i].x & b[j].x) + __popc(a[i].y & b[j].y)
                            + __popc(a[i].z & b[j].z) + __popc(a[i].w & b[j].w);
    }
    __syncthreads();
    int* sRed = (int*)sA;
    #pragma unroll
    for (int i = 0; i < 4; i++)
        #pragma unroll
        for (int j = 0; j < 4; j++)
            sRed[ws*256 + (qx + 4*i)*16 + (px + 4*j)] = acc[i*4+j];
    __syncthreads();
    int s = 0;
    #pragma unroll
    for (int k = 0; k < 16; k++) s += sRed[k*256 + t];
    atomicAdd(&inter[(q0 + (t >> 4))*NQ + p0 + (t & 15)], s);
}

// ---------------- parallel argmax: one warp per q (first-index tie-break) ----------------
__global__ void match_kernel(int round){
    int q = blockIdx.x*8 + (threadIdx.x >> 5);
    int lane = threadIdx.x & 31;
    const int* inter = round ? g_inter2 : g_inter1;
    const int* cb    = g_cnt + (round ? 2*NQ : NQ);
    float ca = (float)(round ? g_cnt2[q] : g_cnt[q]);
    float best = -1.0f; int bi = 0;
    #pragma unroll
    for (int k = 0; k < 2; k++){
        int p = lane + k*32;
        float in = (float)inter[q*NQ + p];
        float un = ca + (float)cb[p] - in;
        float io = in / fmaxf(un, 1.0f);
        if (io > best){ best = io; bi = p; }
    }
    #pragma unroll
    for (int d = 16; d; d >>= 1){
        float ob = __shfl_xor_sync(~0u, best, d);
        int   oi = __shfl_xor_sync(~0u, bi,   d);
        if (ob > best || (ob == best && oi < bi)){ best = ob; bi = oi; }
    }
    if (lane == 0){
        if (round == 0){
            g_idx1[q] = bi; g_m1[q] = best > IOU_T; g_iou1[q] = best;
        } else {
            g_idx2[q] = bi; g_m2[q] = best > IOU_T;
            g_keep[q] = ((g_iou1[q] + best) * 0.5f) > IOU_T;
        }
    }
}

// ---------------- pass 2: merged anchor (fp32-exact bits) + fp16 a1 ----------------
__global__ void mask2_kernel(const float4* __restrict__ vl4){
    int q = blockIdx.y;
    int t = threadIdx.x, lane = t & 31;
    int p = g_idx1[q], m = g_m1[q];
    size_t r0 = (size_t)q * NN4;
    size_t r1 = (size_t)(NQ + p) * NN4;
    #pragma unroll
    for (int j = 0; j < 4; j++){
        int f = blockIdx.x*1024 + j*256 + t;
        float4 v0 = __ldcs(&vl4[r0 + f]);
        float4 a;
        a.x = sigf(v0.x); a.y = sigf(v0.y); a.z = sigf(v0.z); a.w = sigf(v0.w);
        if (m){
            float4 v1 = __ldcs(&vl4[r1 + f]);
            a.x = (a.x + sigf(v1.x)) * 0.5f;
            a.y = (a.y + sigf(v1.y)) * 0.5f;
            a.z = (a.z + sigf(v1.z)) * 0.5f;
            a.w = (a.w + sigf(v1.w)) * 0.5f;
        }
        g_a1[(size_t)q*NN4 + f] = pack4h(a.x, a.y, a.z, a.w);
        unsigned nib = (unsigned)(a.x > 0.5f) | ((unsigned)(a.y > 0.5f) << 1)
                     | ((unsigned)(a.z > 0.5f) << 2) | ((unsigned)(a.w > 0.5f) << 3);
        unsigned part = nib << ((lane & 7) * 4);
        part |= __shfl_xor_sync(~0u, part, 1);
        part |= __shfl_xor_sync(~0u, part, 2);
        part |= __shfl_xor_sync(~0u, part, 4);
        if ((lane & 7) == 0) g_mask2[(size_t)q*NW + (f >> 3)] = part;
    }
}

// ---------------- pass 3: final output ----------------
__global__ void out_kernel(const float4* __restrict__ vl4, float4* __restrict__ out4){
    int q = blockIdx.y;
    int t = threadIdx.x;
    size_t orow4 = (size_t)q * NN4;
    int keep = g_keep[q];
    int m2 = g_m2[q];
    size_t r2 = (size_t)(2*NQ + g_idx2[q]) * NN4;
    #pragma unroll
    for (int j = 0; j < 4; j++){
        int f = blockIdx.x*1024 + j*256 + t;
        float4 o = make_float4(0.f, 0.f, 0.f, 0.f);
        if (keep){
            float4 a = unpack4h(g_a1[(size_t)q*NN4 + f]);   // mostly L2-hit
            if (m2){
                float4 v2 = __ldcs(&vl4[r2 + f]);
                a.x = (a.x*2.f + sigf(v2.x)) * (1.f/3.f);
                a.y = (a.y*2.f + sigf(v2.y)) * (1.f/3.f);
                a.z = (a.z*2.f + sigf(v2.z)) * (1.f/3.f);
                a.w = (a.w*2.f + sigf(v2.w)) * (1.f/3.f);
            }
            unsigned ob = g_occ[f >> 3] >> ((f & 7) * 4);
            o.x = (ob & 1u) ? a.x : 0.f;
            o.y = (ob & 2u) ? a.y : 0.f;
            o.z = (ob & 4u) ? a.z : 0.f;
            o.w = (ob & 8u) ? a.w : 0.f;
        }
        __stcs(&out4[orow4 + f], o);
    }
}

// ---------------- launch (fork-join dual stream) ----------------
extern "C" void kernel_launch(void* const* d_in, const int* in_sizes, int n_in,
                              void* d_out, int out_size){
    const float4* vl4  = (const float4*)d_in[0];   // voxel_logits [3,64,128,128,32]
    const float4* sem4 = (const float4*)d_in[2];   // sem_prob_dense [21,128,128,32]
    float4* out4 = (float4*)d_out;                 // [64,128,128,32]

    // one-time side-stream setup (first call is the uncaptured correctness run)
    static cudaStream_t s1 = 0;
    static cudaEvent_t ev_fork = 0, ev_join = 0;
    static int initd = 0;
    if (!initd){
        if (cudaStreamCreateWithFlags(&s1, cudaStreamNonBlocking) != cudaSuccess) s1 = 0;
        cudaEventCreateWithFlags(&ev_fork, cudaEventDisableTiming);
        cudaEventCreateWithFlags(&ev_join, cudaEventDisableTiming);
        initd = 1;
    }

    init_kernel <<< 16, 256 >>> ();

    if (s1){
        // fork: side stream does occ + mask(s=2), hidden under inter0/match0/mask2
        cudaEventRecord(ev_fork, 0);
        cudaStreamWaitEvent(s1, ev_fork, 0);
        mask_kernel <<< dim3(NN4/1024, NQ, 1), 256, 0, s1 >>> (vl4, 2);
        occ_kernel  <<< NN4/256, 256, 0, s1 >>> (sem4);
        cudaEventRecord(ev_join, s1);

        mask_kernel <<< dim3(NN4/1024, NQ, 2), 256 >>> (vl4, 0);   // s=0,1
        inter_kernel<<< dim3(NW/WCH, NQ/16, NQ/16), 256 >>> (0);
        match_kernel<<< 8, 256 >>> (0);
        mask2_kernel<<< dim3(NN4/1024, NQ), 256 >>> (vl4);
        cudaStreamWaitEvent(0, ev_join, 0);   // need mask s=2 (inter1) + occ (out)
    } else {
        mask_kernel <<< dim3(NN4/1024, NQ, 3), 256 >>> (vl4, 0);
        occ_kernel  <<< NN4/256, 256 >>> (sem4);
        inter_kernel<<< dim3(NW/WCH, NQ/16, NQ/16), 256 >>> (0);
        match_kernel<<< 8, 256 >>> (0);
        mask2_kernel<<< dim3(NN4/1024, NQ), 256 >>> (vl4);
    }

    inter_kernel<<< dim3(NW/WCH, NQ/16, NQ/16), 256 >>> (1);
    match_kernel<<< 8, 256 >>> (1);
    out_kernel  <<< dim3(NN4/1024, NQ), 256 >>> (vl4, out4);
}